// round 5
// baseline (speedup 1.0000x reference)
#include <cuda_runtime.h>
#include <cstdint>

#define BW_   2048
#define NTOK  49
#define DIMC  256
#define C2    128
#define NH    8
#define M_TOT (BW_*NTOK)     // 100352
#define EPSV  1e-5f

#define ASTR 36
#define WSTR 136
#define ASZ  (128*ASTR)
#define WSZ  (32*WSTR)

// ---------------- scratch ----------------
__device__ float g_y1  [(size_t)M_TOT*384];
__device__ float g_xat [(size_t)M_TOT*C2];
__device__ float g_xc  [(size_t)M_TOT*DIMC];
__device__ float g_d   [(size_t)M_TOT*DIMC];
__device__ float g_qkv [(size_t)M_TOT*384];
__device__ float g_xcw [(size_t)M_TOT*C2];
__device__ float g_xat2[(size_t)M_TOT*C2];

__device__ __forceinline__ float wsum(float v) {
    #pragma unroll
    for (int o = 16; o; o >>= 1) v += __shfl_xor_sync(0xffffffffu, v, o);
    return v;
}
__device__ __forceinline__ uint32_t tf32r(float f) {
    uint32_t r; asm("cvt.rna.tf32.f32 %0, %1;" : "=r"(r) : "f"(f)); return r;
}
__device__ __forceinline__ void mma8(float* c, const uint32_t* a, const uint32_t* b) {
    asm volatile(
        "mma.sync.aligned.m16n8k8.row.col.f32.tf32.tf32.f32 "
        "{%0,%1,%2,%3},{%4,%5,%6,%7},{%8,%9},{%0,%1,%2,%3};"
        : "+f"(c[0]), "+f"(c[1]), "+f"(c[2]), "+f"(c[3])
        : "r"(a[0]), "r"(a[1]), "r"(a[2]), "r"(a[3]), "r"(b[0]), "r"(b[1]));
}

// ============== tf32 tensor GEMM: C[M,N] = A[M,K] @ W^T (+bias) ==========
template<int K, bool SPLITA>
__global__ __launch_bounds__(256, 2)
void k_gemm(const float* __restrict__ A0, const float* __restrict__ A1,
            const float* __restrict__ W0, const float* __restrict__ W1, int nsplit,
            const float* __restrict__ bias, float* __restrict__ C, int N)
{
    extern __shared__ uint32_t smu[];
    uint32_t* Asm = smu;              // [2][ASZ]
    uint32_t* Wsm = smu + 2 * ASZ;    // [2][WSZ]
    const int tid  = threadIdx.x;
    const int m0 = blockIdx.y * 128, n0 = blockIdx.x * 128;
    constexpr int NCH = K / 32;
    const int lane = tid & 31, wid = tid >> 5;
    const int g = lane >> 2, r = lane & 3;
    const int mw = (wid & 3) * 32, nw = (wid >> 2) * 64;

    const int arow = tid >> 1, akh = (tid & 1) * 16;
    const int wn = tid & 127, wkh = (tid >> 7) * 16;
    const int wrow = n0 + wn;
    const float* wbase = (wrow < nsplit) ? (W0 + (size_t)wrow * K)
                                         : (W1 + (size_t)(wrow - nsplit) * K);

    float4 ra[4], rw[4];
    auto loadAB = [&](int ch) {
        const int kfA = ch * 32 + akh;
        #pragma unroll
        for (int q = 0; q < 4; ++q) {
            const int kk = kfA + q * 4;
            const float* ap;
            if (SPLITA) ap = (kk < 128) ? (A0 + (size_t)(m0 + arow) * 128 + kk)
                                        : (A1 + (size_t)(m0 + arow) * 128 + kk - 128);
            else        ap = A0 + (size_t)(m0 + arow) * K + kk;
            ra[q] = *(const float4*)ap;
        }
        const int kfW = ch * 32 + wkh;
        #pragma unroll
        for (int q = 0; q < 4; ++q)
            rw[q] = *(const float4*)(wbase + kfW + q * 4);
    };
    auto storeAB = [&](int buf) {
        uint32_t* Ab = Asm + buf * ASZ;
        uint32_t* Wb = Wsm + buf * WSZ;
        #pragma unroll
        for (int q = 0; q < 4; ++q) {
            uint4 t = make_uint4(tf32r(ra[q].x), tf32r(ra[q].y),
                                 tf32r(ra[q].z), tf32r(ra[q].w));
            *(uint4*)(Ab + arow * ASTR + akh + q * 4) = t;
        }
        #pragma unroll
        for (int q = 0; q < 4; ++q) {
            const int kb = wkh + q * 4;
            Wb[(kb + 0) * WSTR + wn] = tf32r(rw[q].x);
            Wb[(kb + 1) * WSTR + wn] = tf32r(rw[q].y);
            Wb[(kb + 2) * WSTR + wn] = tf32r(rw[q].z);
            Wb[(kb + 3) * WSTR + wn] = tf32r(rw[q].w);
        }
    };

    float acc[2][8][4];
    #pragma unroll
    for (int mt = 0; mt < 2; ++mt)
        #pragma unroll
        for (int nt = 0; nt < 8; ++nt)
            #pragma unroll
            for (int e = 0; e < 4; ++e) acc[mt][nt][e] = 0.f;

    loadAB(0);
    storeAB(0);
    __syncthreads();

    for (int ch = 0; ch < NCH; ++ch) {
        if (ch + 1 < NCH) loadAB(ch + 1);
        const uint32_t* Ab = Asm + (ch & 1) * ASZ;
        const uint32_t* Wb = Wsm + (ch & 1) * WSZ;
        #pragma unroll
        for (int ks = 0; ks < 4; ++ks) {
            const int kk = ks * 8;
            uint32_t af[2][4];
            #pragma unroll
            for (int mt = 0; mt < 2; ++mt) {
                const int rb = mw + mt * 16;
                af[mt][0] = Ab[(rb + g)     * ASTR + kk + r];
                af[mt][1] = Ab[(rb + g + 8) * ASTR + kk + r];
                af[mt][2] = Ab[(rb + g)     * ASTR + kk + r + 4];
                af[mt][3] = Ab[(rb + g + 8) * ASTR + kk + r + 4];
            }
            #pragma unroll
            for (int nt = 0; nt < 8; ++nt) {
                uint32_t bf[2];
                const int cb = nw + nt * 8 + g;
                bf[0] = Wb[(kk + r)     * WSTR + cb];
                bf[1] = Wb[(kk + r + 4) * WSTR + cb];
                mma8(acc[0][nt], af[0], bf);
                mma8(acc[1][nt], af[1], bf);
            }
        }
        if (ch + 1 < NCH) {
            __syncthreads();
            storeAB((ch + 1) & 1);
            __syncthreads();
        }
    }

    #pragma unroll
    for (int mt = 0; mt < 2; ++mt) {
        #pragma unroll
        for (int nt = 0; nt < 8; ++nt) {
            const int col = n0 + nw + nt * 8 + 2 * r;
            float b0 = 0.f, b1 = 0.f;
            if (bias) { b0 = bias[col]; b1 = bias[col + 1]; }
            float* c0 = C + (size_t)(m0 + mw + mt * 16 + g) * N + col;
            float* c1 = C + (size_t)(m0 + mw + mt * 16 + g + 8) * N + col;
            *(float2*)c0 = make_float2(acc[mt][nt][0] + b0, acc[mt][nt][1] + b1);
            *(float2*)c1 = make_float2(acc[mt][nt][2] + b0, acc[mt][nt][3] + b1);
        }
    }
}

// ================= E1: dual LayerNorm epilogue of G1 =================
__global__ __launch_bounds__(256)
void k_ln1(const float* __restrict__ pa_b, const float* __restrict__ pa_g,
           const float* __restrict__ pa_be,
           const float* __restrict__ pc_b, const float* __restrict__ pc_g,
           const float* __restrict__ pc_be)
{
    const int row  = blockIdx.x * 8 + (threadIdx.x >> 5);
    const int lane = threadIdx.x & 31;
    const float4* y4 = (const float4*)(g_y1 + (size_t)row * 384);

    float4 va = y4[lane];
    float4 b  = ((const float4*)pa_b)[lane];
    va.x += b.x; va.y += b.y; va.z += b.z; va.w += b.w;
    float m = wsum(va.x + va.y + va.z + va.w) * (1.f / 128.f);
    va.x -= m; va.y -= m; va.z -= m; va.w -= m;
    float inv = rsqrtf(wsum(va.x*va.x + va.y*va.y + va.z*va.z + va.w*va.w) * (1.f / 128.f) + EPSV);
    float4 g  = ((const float4*)pa_g)[lane];
    float4 be = ((const float4*)pa_be)[lane];
    float4 o;
    o.x = va.x * inv * g.x + be.x; o.y = va.y * inv * g.y + be.y;
    o.z = va.z * inv * g.z + be.z; o.w = va.w * inv * g.w + be.w;
    *(float4*)(g_xat + (size_t)row * 128 + lane * 4) = o;

    float4 c0 = y4[32 + lane], c1 = y4[64 + lane];
    float4 b0 = ((const float4*)pc_b)[lane], b1 = ((const float4*)pc_b)[32 + lane];
    c0.x += b0.x; c0.y += b0.y; c0.z += b0.z; c0.w += b0.w;
    c1.x += b1.x; c1.y += b1.y; c1.z += b1.z; c1.w += b1.w;
    m = wsum(c0.x + c0.y + c0.z + c0.w + c1.x + c1.y + c1.z + c1.w) * (1.f / 256.f);
    c0.x -= m; c0.y -= m; c0.z -= m; c0.w -= m;
    c1.x -= m; c1.y -= m; c1.z -= m; c1.w -= m;
    inv = rsqrtf(wsum(c0.x*c0.x + c0.y*c0.y + c0.z*c0.z + c0.w*c0.w +
                      c1.x*c1.x + c1.y*c1.y + c1.z*c1.z + c1.w*c1.w) * (1.f / 256.f) + EPSV);
    float4 g0 = ((const float4*)pc_g)[lane],  g1 = ((const float4*)pc_g)[32 + lane];
    float4 e0 = ((const float4*)pc_be)[lane], e1 = ((const float4*)pc_be)[32 + lane];
    float4 o0, o1;
    o0.x = c0.x * inv * g0.x + e0.x; o0.y = c0.y * inv * g0.y + e0.y;
    o0.z = c0.z * inv * g0.z + e0.z; o0.w = c0.w * inv * g0.w + e0.w;
    o1.x = c1.x * inv * g1.x + e1.x; o1.y = c1.y * inv * g1.y + e1.y;
    o1.z = c1.z * inv * g1.z + e1.z; o1.w = c1.w * inv * g1.w + e1.w;
    *(float4*)(g_xc + (size_t)row * 256 + lane * 4)       = o0;
    *(float4*)(g_xc + (size_t)row * 256 + 128 + lane * 4) = o1;
}

// ================= D: depthwise 3x3 + BN + GELU (128-ch blocks) ==========
__global__ __launch_bounds__(256)
void k_dw(const float* __restrict__ dw_w, const float* __restrict__ dw_b,
          const float* __restrict__ bn_g, const float* __restrict__ bn_b,
          const float* __restrict__ bn_m, const float* __restrict__ bn_v)
{
    extern __shared__ float sm[];   // 81 pixels x 128 ch = 41,472 B
    const int bw = blockIdx.x >> 1, half = blockIdx.x & 1;
    const int cb = half * 128;
    const int tid = threadIdx.x;
    const int b = bw >> 6, wi = bw & 63, wr = wi >> 3, wc = wi & 7;

    for (int i = tid; i < 81 * 32; i += 256) {
        int pix = i >> 5, c4 = i & 31;
        int gy = wr * 7 + pix / 9 - 1, gx = wc * 7 + pix % 9 - 1;
        float4 v = make_float4(0.f, 0.f, 0.f, 0.f);
        if ((unsigned)gy < 56u && (unsigned)gx < 56u) {
            int wn = b * 64 + (gy / 7) * 8 + gx / 7;
            int tk = (gy % 7) * 7 + gx % 7;
            v = *(const float4*)(g_xc + ((size_t)wn * 49 + tk) * 256 + cb + c4 * 4);
        }
        *(float4*)(sm + pix * 128 + c4 * 4) = v;
    }
    __syncthreads();

    const int c  = tid & 127;       // channel within half
    const int ph = tid >> 7;        // pixel parity
    const int cg = cb + c;
    float w[9];
    #pragma unroll
    for (int j = 0; j < 9; ++j) w[j] = dw_w[cg * 9 + j];
    const float sc = bn_g[cg] * rsqrtf(bn_v[cg] + EPSV);
    const float sh = bn_b[cg] - bn_m[cg] * sc;
    const float db = dw_b[cg];
    float* outp = g_d + (size_t)bw * 49 * 256 + cb;

    #pragma unroll
    for (int q = 0; q < 25; ++q) {
        const int p = ph + 2 * q;
        if (p < 49) {
            const int oy = p / 7, ox = p % 7;
            float acc = db;
            #pragma unroll
            for (int dy = 0; dy < 3; ++dy)
                #pragma unroll
                for (int dx = 0; dx < 3; ++dx)
                    acc += w[dy * 3 + dx] * sm[((oy + dy) * 9 + ox + dx) * 128 + c];
            float v = acc * sc + sh;
            outp[p * 256 + c] = 0.5f * v * (1.0f + erff(v * 0.70710678118654752f));
        }
    }
}

// ================= A: windowed MHSA + LN =================
__global__ __launch_bounds__(256)
void k_attn(const float* __restrict__ rpb,
            const float* __restrict__ an_g, const float* __restrict__ an_be)
{
    extern __shared__ float sm[];
    float* kvs  = sm;                 // 49*256 (k | v)
    float* ss   = sm + 49 * 256;      // 8*32*53 scores
    float* rpbs = ss + 8 * 32 * 53;   // 1352
    const int bw = blockIdx.x, tid = threadIdx.x;
    const int h = tid >> 5, lane = tid & 31;
    const float* qkvw = g_qkv + (size_t)bw * 49 * 384;

    for (int i = tid; i < 49 * 64; i += 256) {
        int r = i >> 6, cc = i & 63;
        *(float4*)(kvs + r * 256 + cc * 4) = *(const float4*)(qkvw + r * 384 + 128 + cc * 4);
    }
    for (int i = tid; i < 1352; i += 256) rpbs[i] = rpb[i];
    __syncthreads();

    float o[2][16];
    #pragma unroll
    for (int pass = 0; pass < 2; ++pass) {
        const int n = pass * 32 + lane;
        if (n < 49) {
            float4 q0, q1, q2, q3;
            const float4* qp = (const float4*)(qkvw + n * 384 + h * 16);
            q0 = qp[0]; q1 = qp[1]; q2 = qp[2]; q3 = qp[3];
            const int yn = n / 7, xn = n % 7;
            float* sr = ss + (h * 32 + lane) * 53;
            float mx = -1e30f;
            #pragma unroll 7
            for (int m2 = 0; m2 < 49; ++m2) {
                const float4* kr = (const float4*)(kvs + m2 * 256 + h * 16);
                float4 k0 = kr[0], k1 = kr[1], k2 = kr[2], k3 = kr[3];
                float s = q0.x*k0.x + q0.y*k0.y + q0.z*k0.z + q0.w*k0.w
                        + q1.x*k1.x + q1.y*k1.y + q1.z*k1.z + q1.w*k1.w
                        + q2.x*k2.x + q2.y*k2.y + q2.z*k2.z + q2.w*k2.w
                        + q3.x*k3.x + q3.y*k3.y + q3.z*k3.z + q3.w*k3.w;
                int dy = yn - m2 / 7 + 6, dx = xn - m2 % 7 + 6;
                s = s * 0.25f + rpbs[(dy * 13 + dx) * NH + h];
                sr[m2] = s; mx = fmaxf(mx, s);
            }
            float sum = 0.f;
            #pragma unroll 7
            for (int m2 = 0; m2 < 49; ++m2) {
                float e = __expf(sr[m2] - mx);
                sr[m2] = e; sum += e;
            }
            const float inv = 1.f / sum;
            float* op = o[pass];
            #pragma unroll
            for (int d = 0; d < 16; ++d) op[d] = 0.f;
            #pragma unroll 7
            for (int m2 = 0; m2 < 49; ++m2) {
                const float p = sr[m2];
                const float4* vr = (const float4*)(kvs + m2 * 256 + 128 + h * 16);
                float4 v0 = vr[0], v1 = vr[1], v2 = vr[2], v3 = vr[3];
                op[0]  += p * v0.x; op[1]  += p * v0.y; op[2]  += p * v0.z; op[3]  += p * v0.w;
                op[4]  += p * v1.x; op[5]  += p * v1.y; op[6]  += p * v1.z; op[7]  += p * v1.w;
                op[8]  += p * v2.x; op[9]  += p * v2.y; op[10] += p * v2.z; op[11] += p * v2.w;
                op[12] += p * v3.x; op[13] += p * v3.y; op[14] += p * v3.z; op[15] += p * v3.w;
            }
            #pragma unroll
            for (int d = 0; d < 16; ++d) op[d] *= inv;
        }
    }
    __syncthreads();
    float* xo = kvs;
    #pragma unroll
    for (int pass = 0; pass < 2; ++pass) {
        const int n = pass * 32 + lane;
        if (n < 49) {
            #pragma unroll
            for (int d = 0; d < 16; ++d) xo[n * 128 + h * 16 + d] = o[pass][d];
        }
    }
    __syncthreads();

    for (int r = h; r < 49; r += 8) {
        float4 v = *(float4*)(xo + r * 128 + lane * 4);
        float m = wsum(v.x + v.y + v.z + v.w) * (1.f / 128.f);
        v.x -= m; v.y -= m; v.z -= m; v.w -= m;
        float inv = rsqrtf(wsum(v.x*v.x + v.y*v.y + v.z*v.z + v.w*v.w) * (1.f / 128.f) + EPSV);
        float4 g  = ((const float4*)an_g)[lane];
        float4 be = ((const float4*)an_be)[lane];
        float4 out;
        out.x = v.x * inv * g.x + be.x; out.y = v.y * inv * g.y + be.y;
        out.z = v.z * inv * g.z + be.z; out.w = v.w * inv * g.w + be.w;
        *(float4*)(g_xat2 + ((size_t)bw * 49 + r) * 128 + lane * 4) = out;
    }
}

// ================= host launch =================
extern "C" void kernel_launch(void* const* d_in, const int* in_sizes, int n_in,
                              void* d_out, int out_size)
{
    const float* x     = (const float*)d_in[0];
    const float* rpb   = (const float*)d_in[1];
    const float* pa_w  = (const float*)d_in[2];
    const float* pa_b  = (const float*)d_in[3];
    const float* pa_g  = (const float*)d_in[4];
    const float* pa_be = (const float*)d_in[5];
    const float* pc_w  = (const float*)d_in[6];
    const float* pc_b  = (const float*)d_in[7];
    const float* pc_g  = (const float*)d_in[8];
    const float* pc_be = (const float*)d_in[9];
    const float* dw_w  = (const float*)d_in[10];
    const float* dw_b  = (const float*)d_in[11];
    const float* bn_g  = (const float*)d_in[12];
    const float* bn_b  = (const float*)d_in[13];
    const float* bn_m  = (const float*)d_in[14];
    const float* bn_v  = (const float*)d_in[15];
    const float* pr_w  = (const float*)d_in[16];
    const float* pr_b  = (const float*)d_in[17];
    const float* qkv_w = (const float*)d_in[18];
    const float* qkv_b = (const float*)d_in[19];
    const float* an_g  = (const float*)d_in[20];
    const float* an_be = (const float*)d_in[21];
    const float* po_w  = (const float*)d_in[22];
    const float* po_b  = (const float*)d_in[23];

    float *py1, *pxat, *pxc, *pd, *pqkv, *pxcw, *pxat2;
    cudaGetSymbolAddress((void**)&py1,   g_y1);
    cudaGetSymbolAddress((void**)&pxat,  g_xat);
    cudaGetSymbolAddress((void**)&pxc,   g_xc);
    cudaGetSymbolAddress((void**)&pd,    g_d);
    cudaGetSymbolAddress((void**)&pqkv,  g_qkv);
    cudaGetSymbolAddress((void**)&pxcw,  g_xcw);
    cudaGetSymbolAddress((void**)&pxat2, g_xat2);

    const int smG = (2 * ASZ + 2 * WSZ) * 4;      // 71,680
    const int smD = 81 * 128 * 4;                 // 41,472
    const int smA = (49*256 + 8*32*53 + 1352) * 4;// 109,856

    cudaFuncSetAttribute(k_gemm<256,false>, cudaFuncAttributeMaxDynamicSharedMemorySize, smG);
    cudaFuncSetAttribute(k_gemm<128,false>, cudaFuncAttributeMaxDynamicSharedMemorySize, smG);
    cudaFuncSetAttribute(k_gemm<256,true>,  cudaFuncAttributeMaxDynamicSharedMemorySize, smG);
    cudaFuncSetAttribute(k_dw,   cudaFuncAttributeMaxDynamicSharedMemorySize, smD);
    cudaFuncSetAttribute(k_attn, cudaFuncAttributeMaxDynamicSharedMemorySize, smA);

    const int MT = M_TOT / 128;   // 784

    // G1: x @ [pa_w; pc_w]^T -> g_y1 (bias deferred to LN)
    k_gemm<256,false><<<dim3(3, MT), 256, smG>>>(x, nullptr, pa_w, pc_w, 128,
                                                 nullptr, py1, 384);
    // E1: dual LN -> g_xat, g_xc
    k_ln1<<<M_TOT/8, 256>>>(pa_b, pa_g, pa_be, pc_b, pc_g, pc_be);
    // G3: qkv = g_xat @ qkv_w^T + qkv_b
    k_gemm<128,false><<<dim3(3, MT), 256, smG>>>(pxat, nullptr, qkv_w, qkv_w, 1<<30,
                                                 qkv_b, pqkv, 384);
    // D: dwconv + BN + GELU -> g_d
    k_dw<<<BW_ * 2, 256, smD>>>(dw_w, dw_b, bn_g, bn_b, bn_m, bn_v);
    // G2: 1x1 conv: g_d @ pr_w^T + pr_b -> g_xcw
    k_gemm<256,false><<<dim3(1, MT), 256, smG>>>(pd, nullptr, pr_w, pr_w, 1<<30,
                                                 pr_b, pxcw, 128);
    // A: attention + LN -> g_xat2
    k_attn<<<BW_, 256, smA>>>(rpb, an_g, an_be);
    // G4: concat(g_xat2, g_xcw) @ po_w^T + po_b -> out
    k_gemm<256,true><<<dim3(2, MT), 256, smG>>>(pxat2, pxcw, po_w, po_w, 1<<30,
                                                po_b, (float*)d_out, 256);
}

// round 7
// speedup vs baseline: 1.1858x; 1.1858x over previous
#include <cuda_runtime.h>
#include <cuda_fp16.h>
#include <cstdint>

#define BW_   2048
#define NTOK  49
#define DIMC  256
#define C2    128
#define NH    8
#define M_TOT (BW_*NTOK)     // 100352
#define EPSV  1e-5f

// fp16 GEMM smem geometry (u32 words)
#define ASTRW 20              // A: 32 halves (16 words) + 4 pad words per row
#define WSTRW 136             // B: 128 cols + 8 pad per k-pair row
#define ASZW  (128*ASTRW)     // 2560 words / buffer
#define WSZW  (16*WSTRW)      // 2176 words / buffer

// ---------------- scratch ----------------
__device__ float g_y1  [(size_t)M_TOT*384];
__device__ float g_xat [(size_t)M_TOT*C2];
__device__ float g_xc  [(size_t)M_TOT*DIMC];
__device__ float g_d   [(size_t)M_TOT*DIMC];
__device__ float g_qkv [(size_t)M_TOT*384];
__device__ float g_xcw [(size_t)M_TOT*C2];
__device__ float g_xat2[(size_t)M_TOT*C2];

__device__ __forceinline__ float wsum(float v) {
    #pragma unroll
    for (int o = 16; o; o >>= 1) v += __shfl_xor_sync(0xffffffffu, v, o);
    return v;
}
__device__ __forceinline__ uint32_t h2u(float a, float b) {
    __half2 h = __floats2half2_rn(a, b);
    uint32_t u; *(__half2*)&u = h; return u;
}
__device__ __forceinline__ void mma16(float* c, const uint32_t* a,
                                      uint32_t b0, uint32_t b1) {
    asm volatile(
        "mma.sync.aligned.m16n8k16.row.col.f32.f16.f16.f32 "
        "{%0,%1,%2,%3},{%4,%5,%6,%7},{%8,%9},{%0,%1,%2,%3};"
        : "+f"(c[0]), "+f"(c[1]), "+f"(c[2]), "+f"(c[3])
        : "r"(a[0]), "r"(a[1]), "r"(a[2]), "r"(a[3]), "r"(b0), "r"(b1));
}

// ============== fp16 tensor GEMM: C[M,N] = A[M,K] @ W^T (+bias) ==========
// 128x128 CTA tile; 8 warps each m32 x n64; k-chunks of 32 (2 x k16 steps).
template<int K, bool SPLITA>
__global__ __launch_bounds__(256)
void k_gemm(const float* __restrict__ A0, const float* __restrict__ A1,
            const float* __restrict__ W0, const float* __restrict__ W1, int nsplit,
            const float* __restrict__ bias, float* __restrict__ C, int N)
{
    extern __shared__ uint32_t smu[];
    uint32_t* Asm = smu;               // [2][ASZW]
    uint32_t* Wsm = smu + 2 * ASZW;    // [2][WSZW]
    const int tid = threadIdx.x;
    const int m0 = blockIdx.y * 128, n0 = blockIdx.x * 128;
    constexpr int NCH = K / 32;
    const int lane = tid & 31, wid = tid >> 5;
    const int g = lane >> 2, r = lane & 3;
    const int mw = (wid & 3) * 32, nw = (wid >> 2) * 64;

    // staging indices
    const int arow = tid >> 1, akh = (tid & 1) * 16;   // 16 halves each
    const int wn = tid & 127, wkh = (tid >> 7) * 16;
    const int wrow = n0 + wn;
    const float* wbase = (wrow < nsplit) ? (W0 + (size_t)wrow * K)
                                         : (W1 + (size_t)(wrow - nsplit) * K);

    float4 ra[4], rw[4];
    auto loadAB = [&](int ch) {
        const int kfA = ch * 32 + akh;
        #pragma unroll
        for (int q = 0; q < 4; ++q) {
            const int kk = kfA + q * 4;
            const float* ap;
            if (SPLITA) ap = (kk < 128) ? (A0 + (size_t)(m0 + arow) * 128 + kk)
                                        : (A1 + (size_t)(m0 + arow) * 128 + kk - 128);
            else        ap = A0 + (size_t)(m0 + arow) * K + kk;
            ra[q] = *(const float4*)ap;
        }
        const int kfW = ch * 32 + wkh;
        #pragma unroll
        for (int q = 0; q < 4; ++q)
            rw[q] = *(const float4*)(wbase + kfW + q * 4);
    };
    auto storeAB = [&](int buf) {
        uint32_t* Ab = Asm + buf * ASZW;
        uint32_t* Wb = Wsm + buf * WSZW;
        #pragma unroll
        for (int q = 0; q < 4; ++q) {
            uint2 t = make_uint2(h2u(ra[q].x, ra[q].y), h2u(ra[q].z, ra[q].w));
            *(uint2*)(Ab + arow * ASTRW + (tid & 1) * 8 + q * 2) = t;
        }
        #pragma unroll
        for (int q = 0; q < 4; ++q) {
            const int kp = (wkh + q * 4) >> 1;     // k-pair row
            Wb[kp * WSTRW + wn]       = h2u(rw[q].x, rw[q].y);
            Wb[(kp + 1) * WSTRW + wn] = h2u(rw[q].z, rw[q].w);
        }
    };

    float acc[2][8][4];
    #pragma unroll
    for (int mt = 0; mt < 2; ++mt)
        #pragma unroll
        for (int nt = 0; nt < 8; ++nt)
            #pragma unroll
            for (int e = 0; e < 4; ++e) acc[mt][nt][e] = 0.f;

    loadAB(0);
    storeAB(0);
    __syncthreads();

    for (int ch = 0; ch < NCH; ++ch) {
        if (ch + 1 < NCH) loadAB(ch + 1);
        const uint32_t* Ab = Asm + (ch & 1) * ASZW;
        const uint32_t* Wb = Wsm + (ch & 1) * WSZW;
        #pragma unroll
        for (int ks = 0; ks < 2; ++ks) {
            const int kp = ks * 8;          // k-pair base (k16 step)
            uint32_t af[2][4];
            #pragma unroll
            for (int mt = 0; mt < 2; ++mt) {
                const int rb = mw + mt * 16;
                af[mt][0] = Ab[(rb + g)     * ASTRW + kp + r];
                af[mt][1] = Ab[(rb + g + 8) * ASTRW + kp + r];
                af[mt][2] = Ab[(rb + g)     * ASTRW + kp + r + 4];
                af[mt][3] = Ab[(rb + g + 8) * ASTRW + kp + r + 4];
            }
            #pragma unroll
            for (int nt = 0; nt < 8; ++nt) {
                const int cb = nw + nt * 8 + g;
                const uint32_t b0 = Wb[(kp + r)     * WSTRW + cb];
                const uint32_t b1 = Wb[(kp + r + 4) * WSTRW + cb];
                mma16(acc[0][nt], af[0], b0, b1);
                mma16(acc[1][nt], af[1], b0, b1);
            }
        }
        if (ch + 1 < NCH) {
            __syncthreads();
            storeAB((ch + 1) & 1);
            __syncthreads();
        }
    }

    #pragma unroll
    for (int mt = 0; mt < 2; ++mt) {
        #pragma unroll
        for (int nt = 0; nt < 8; ++nt) {
            const int col = n0 + nw + nt * 8 + 2 * r;
            float b0 = 0.f, b1 = 0.f;
            if (bias) { b0 = bias[col]; b1 = bias[col + 1]; }
            float* c0 = C + (size_t)(m0 + mw + mt * 16 + g) * N + col;
            float* c1 = C + (size_t)(m0 + mw + mt * 16 + g + 8) * N + col;
            *(float2*)c0 = make_float2(acc[mt][nt][0] + b0, acc[mt][nt][1] + b1);
            *(float2*)c1 = make_float2(acc[mt][nt][2] + b0, acc[mt][nt][3] + b1);
        }
    }
}

// ================= E1: dual LayerNorm epilogue of G1 =================
__global__ __launch_bounds__(256)
void k_ln1(const float* __restrict__ pa_b, const float* __restrict__ pa_g,
           const float* __restrict__ pa_be,
           const float* __restrict__ pc_b, const float* __restrict__ pc_g,
           const float* __restrict__ pc_be)
{
    const int row  = blockIdx.x * 8 + (threadIdx.x >> 5);
    const int lane = threadIdx.x & 31;
    const float4* y4 = (const float4*)(g_y1 + (size_t)row * 384);

    float4 va = y4[lane];
    float4 b  = ((const float4*)pa_b)[lane];
    va.x += b.x; va.y += b.y; va.z += b.z; va.w += b.w;
    float m = wsum(va.x + va.y + va.z + va.w) * (1.f / 128.f);
    va.x -= m; va.y -= m; va.z -= m; va.w -= m;
    float inv = rsqrtf(wsum(va.x*va.x + va.y*va.y + va.z*va.z + va.w*va.w) * (1.f / 128.f) + EPSV);
    float4 g  = ((const float4*)pa_g)[lane];
    float4 be = ((const float4*)pa_be)[lane];
    float4 o;
    o.x = va.x * inv * g.x + be.x; o.y = va.y * inv * g.y + be.y;
    o.z = va.z * inv * g.z + be.z; o.w = va.w * inv * g.w + be.w;
    *(float4*)(g_xat + (size_t)row * 128 + lane * 4) = o;

    float4 c0 = y4[32 + lane], c1 = y4[64 + lane];
    float4 b0 = ((const float4*)pc_b)[lane], b1 = ((const float4*)pc_b)[32 + lane];
    c0.x += b0.x; c0.y += b0.y; c0.z += b0.z; c0.w += b0.w;
    c1.x += b1.x; c1.y += b1.y; c1.z += b1.z; c1.w += b1.w;
    m = wsum(c0.x + c0.y + c0.z + c0.w + c1.x + c1.y + c1.z + c1.w) * (1.f / 256.f);
    c0.x -= m; c0.y -= m; c0.z -= m; c0.w -= m;
    c1.x -= m; c1.y -= m; c1.z -= m; c1.w -= m;
    inv = rsqrtf(wsum(c0.x*c0.x + c0.y*c0.y + c0.z*c0.z + c0.w*c0.w +
                      c1.x*c1.x + c1.y*c1.y + c1.z*c1.z + c1.w*c1.w) * (1.f / 256.f) + EPSV);
    float4 g0 = ((const float4*)pc_g)[lane],  g1 = ((const float4*)pc_g)[32 + lane];
    float4 e0 = ((const float4*)pc_be)[lane], e1 = ((const float4*)pc_be)[32 + lane];
    float4 o0, o1;
    o0.x = c0.x * inv * g0.x + e0.x; o0.y = c0.y * inv * g0.y + e0.y;
    o0.z = c0.z * inv * g0.z + e0.z; o0.w = c0.w * inv * g0.w + e0.w;
    o1.x = c1.x * inv * g1.x + e1.x; o1.y = c1.y * inv * g1.y + e1.y;
    o1.z = c1.z * inv * g1.z + e1.z; o1.w = c1.w * inv * g1.w + e1.w;
    *(float4*)(g_xc + (size_t)row * 256 + lane * 4)       = o0;
    *(float4*)(g_xc + (size_t)row * 256 + 128 + lane * 4) = o1;
}

// ================= D: depthwise 3x3 + BN + GELU (compile-time offsets) ====
__global__ __launch_bounds__(256)
void k_dw(const float* __restrict__ dw_w, const float* __restrict__ dw_b,
          const float* __restrict__ bn_g, const float* __restrict__ bn_b,
          const float* __restrict__ bn_m, const float* __restrict__ bn_v)
{
    extern __shared__ float sm[];   // 81 pixels x 128 ch
    const int bw = blockIdx.x >> 1, half = blockIdx.x & 1;
    const int cb = half * 128;
    const int tid = threadIdx.x;
    const int b = bw >> 6, wi = bw & 63, wr = wi >> 3, wc = wi & 7;

    for (int i = tid; i < 81 * 32; i += 256) {
        int pix = i >> 5, c4 = i & 31;
        int gy = wr * 7 + pix / 9 - 1, gx = wc * 7 + pix % 9 - 1;
        float4 v = make_float4(0.f, 0.f, 0.f, 0.f);
        if ((unsigned)gy < 56u && (unsigned)gx < 56u) {
            int wn = b * 64 + (gy / 7) * 8 + gx / 7;
            int tk = (gy % 7) * 7 + gx % 7;
            v = *(const float4*)(g_xc + ((size_t)wn * 49 + tk) * 256 + cb + c4 * 4);
        }
        *(float4*)(sm + pix * 128 + c4 * 4) = v;
    }
    __syncthreads();

    const int c  = tid & 127;
    const int ph = tid >> 7;
    const int cg = cb + c;
    float w[9];
    #pragma unroll
    for (int j = 0; j < 9; ++j) w[j] = dw_w[cg * 9 + j];
    const float sc = bn_g[cg] * rsqrtf(bn_v[cg] + EPSV);
    const float sh = bn_b[cg] - bn_m[cg] * sc;
    const float db = dw_b[cg];
    const float* smc = sm + c;
    float* outc = g_d + (size_t)bw * 49 * 256 + cb + c;

    auto dopix = [&](int p) {
        const int oy = p / 7, ox = p % 7;   // compile-time when p is constant
        float acc = db;
        #pragma unroll
        for (int dy = 0; dy < 3; ++dy)
            #pragma unroll
            for (int dx = 0; dx < 3; ++dx)
                acc += w[dy * 3 + dx] * smc[((oy + dy) * 9 + ox + dx) * 128];
        float v = acc * sc + sh;
        outc[p * 256] = 0.5f * v * (1.0f + erff(v * 0.70710678118654752f));
    };
    if (ph == 0) {
        #pragma unroll
        for (int q = 0; q < 25; ++q) dopix(2 * q);
    } else {
        #pragma unroll
        for (int q = 0; q < 24; ++q) dopix(2 * q + 1);
    }
}

// ================= A: windowed MHSA + LN =================
__global__ __launch_bounds__(256)
void k_attn(const float* __restrict__ rpb,
            const float* __restrict__ an_g, const float* __restrict__ an_be)
{
    extern __shared__ float sm[];
    float* kvs  = sm;                 // 49*256 (k | v)
    float* ss   = sm + 49 * 256;      // 8*32*53 scores
    float* rpbs = ss + 8 * 32 * 53;   // 1352
    const int bw = blockIdx.x, tid = threadIdx.x;
    const int h = tid >> 5, lane = tid & 31;
    const float* qkvw = g_qkv + (size_t)bw * 49 * 384;

    for (int i = tid; i < 49 * 64; i += 256) {
        int r = i >> 6, cc = i & 63;
        *(float4*)(kvs + r * 256 + cc * 4) = *(const float4*)(qkvw + r * 384 + 128 + cc * 4);
    }
    for (int i = tid; i < 1352; i += 256) rpbs[i] = rpb[i];
    __syncthreads();

    float o[2][16];
    #pragma unroll
    for (int pass = 0; pass < 2; ++pass) {
        const int n = pass * 32 + lane;
        if (n < 49) {
            float4 q0, q1, q2, q3;
            const float4* qp = (const float4*)(qkvw + n * 384 + h * 16);
            q0 = qp[0]; q1 = qp[1]; q2 = qp[2]; q3 = qp[3];
            const int yn = n / 7, xn = n % 7;
            float* sr = ss + (h * 32 + lane) * 53;
            float mx = -1e30f;
            #pragma unroll 7
            for (int m2 = 0; m2 < 49; ++m2) {
                const float4* kr = (const float4*)(kvs + m2 * 256 + h * 16);
                float4 k0 = kr[0], k1 = kr[1], k2 = kr[2], k3 = kr[3];
                float s = q0.x*k0.x + q0.y*k0.y + q0.z*k0.z + q0.w*k0.w
                        + q1.x*k1.x + q1.y*k1.y + q1.z*k1.z + q1.w*k1.w
                        + q2.x*k2.x + q2.y*k2.y + q2.z*k2.z + q2.w*k2.w
                        + q3.x*k3.x + q3.y*k3.y + q3.z*k3.z + q3.w*k3.w;
                int dy = yn - m2 / 7 + 6, dx = xn - m2 % 7 + 6;
                s = s * 0.25f + rpbs[(dy * 13 + dx) * NH + h];
                sr[m2] = s; mx = fmaxf(mx, s);
            }
            float sum = 0.f;
            #pragma unroll 7
            for (int m2 = 0; m2 < 49; ++m2) {
                float e = __expf(sr[m2] - mx);
                sr[m2] = e; sum += e;
            }
            const float inv = 1.f / sum;
            float* op = o[pass];
            #pragma unroll
            for (int d = 0; d < 16; ++d) op[d] = 0.f;
            #pragma unroll 7
            for (int m2 = 0; m2 < 49; ++m2) {
                const float p = sr[m2];
                const float4* vr = (const float4*)(kvs + m2 * 256 + 128 + h * 16);
                float4 v0 = vr[0], v1 = vr[1], v2 = vr[2], v3 = vr[3];
                op[0]  += p * v0.x; op[1]  += p * v0.y; op[2]  += p * v0.z; op[3]  += p * v0.w;
                op[4]  += p * v1.x; op[5]  += p * v1.y; op[6]  += p * v1.z; op[7]  += p * v1.w;
                op[8]  += p * v2.x; op[9]  += p * v2.y; op[10] += p * v2.z; op[11] += p * v2.w;
                op[12] += p * v3.x; op[13] += p * v3.y; op[14] += p * v3.z; op[15] += p * v3.w;
            }
            #pragma unroll
            for (int d = 0; d < 16; ++d) op[d] *= inv;
        }
    }
    __syncthreads();
    float* xo = kvs;
    #pragma unroll
    for (int pass = 0; pass < 2; ++pass) {
        const int n = pass * 32 + lane;
        if (n < 49) {
            #pragma unroll
            for (int d = 0; d < 16; ++d) xo[n * 128 + h * 16 + d] = o[pass][d];
        }
    }
    __syncthreads();

    for (int r = h; r < 49; r += 8) {
        float4 v = *(float4*)(xo + r * 128 + lane * 4);
        float m = wsum(v.x + v.y + v.z + v.w) * (1.f / 128.f);
        v.x -= m; v.y -= m; v.z -= m; v.w -= m;
        float inv = rsqrtf(wsum(v.x*v.x + v.y*v.y + v.z*v.z + v.w*v.w) * (1.f / 128.f) + EPSV);
        float4 g  = ((const float4*)an_g)[lane];
        float4 be = ((const float4*)an_be)[lane];
        float4 out;
        out.x = v.x * inv * g.x + be.x; out.y = v.y * inv * g.y + be.y;
        out.z = v.z * inv * g.z + be.z; out.w = v.w * inv * g.w + be.w;
        *(float4*)(g_xat2 + ((size_t)bw * 49 + r) * 128 + lane * 4) = out;
    }
}

// ================= host launch =================
extern "C" void kernel_launch(void* const* d_in, const int* in_sizes, int n_in,
                              void* d_out, int out_size)
{
    const float* x     = (const float*)d_in[0];
    const float* rpb   = (const float*)d_in[1];
    const float* pa_w  = (const float*)d_in[2];
    const float* pa_b  = (const float*)d_in[3];
    const float* pa_g  = (const float*)d_in[4];
    const float* pa_be = (const float*)d_in[5];
    const float* pc_w  = (const float*)d_in[6];
    const float* pc_b  = (const float*)d_in[7];
    const float* pc_g  = (const float*)d_in[8];
    const float* pc_be = (const float*)d_in[9];
    const float* dw_w  = (const float*)d_in[10];
    const float* dw_b  = (const float*)d_in[11];
    const float* bn_g  = (const float*)d_in[12];
    const float* bn_b  = (const float*)d_in[13];
    const float* bn_m  = (const float*)d_in[14];
    const float* bn_v  = (const float*)d_in[15];
    const float* pr_w  = (const float*)d_in[16];
    const float* pr_b  = (const float*)d_in[17];
    const float* qkv_w = (const float*)d_in[18];
    const float* qkv_b = (const float*)d_in[19];
    const float* an_g  = (const float*)d_in[20];
    const float* an_be = (const float*)d_in[21];
    const float* po_w  = (const float*)d_in[22];
    const float* po_b  = (const float*)d_in[23];

    float *py1, *pxat, *pxc, *pd, *pqkv, *pxcw, *pxat2;
    cudaGetSymbolAddress((void**)&py1,   g_y1);
    cudaGetSymbolAddress((void**)&pxat,  g_xat);
    cudaGetSymbolAddress((void**)&pxc,   g_xc);
    cudaGetSymbolAddress((void**)&pd,    g_d);
    cudaGetSymbolAddress((void**)&pqkv,  g_qkv);
    cudaGetSymbolAddress((void**)&pxcw,  g_xcw);
    cudaGetSymbolAddress((void**)&pxat2, g_xat2);

    const int smG = (2 * ASZW + 2 * WSZW) * 4;    // 37,888
    const int smD = 81 * 128 * 4;                 // 41,472
    const int smA = (49*256 + 8*32*53 + 1352) * 4;// 109,856

    cudaFuncSetAttribute(k_gemm<256,false>, cudaFuncAttributeMaxDynamicSharedMemorySize, smG);
    cudaFuncSetAttribute(k_gemm<128,false>, cudaFuncAttributeMaxDynamicSharedMemorySize, smG);
    cudaFuncSetAttribute(k_gemm<256,true>,  cudaFuncAttributeMaxDynamicSharedMemorySize, smG);
    cudaFuncSetAttribute(k_dw,   cudaFuncAttributeMaxDynamicSharedMemorySize, smD);
    cudaFuncSetAttribute(k_attn, cudaFuncAttributeMaxDynamicSharedMemorySize, smA);

    const int MT = M_TOT / 128;   // 784

    // G1: x @ [pa_w; pc_w]^T -> g_y1 (bias deferred to LN)
    k_gemm<256,false><<<dim3(3, MT), 256, smG>>>(x, nullptr, pa_w, pc_w, 128,
                                                 nullptr, py1, 384);
    // E1: dual LN -> g_xat, g_xc
    k_ln1<<<M_TOT/8, 256>>>(pa_b, pa_g, pa_be, pc_b, pc_g, pc_be);
    // G3: qkv = g_xat @ qkv_w^T + qkv_b
    k_gemm<128,false><<<dim3(3, MT), 256, smG>>>(pxat, nullptr, qkv_w, qkv_w, 1<<30,
                                                 qkv_b, pqkv, 384);
    // D: dwconv + BN + GELU -> g_d
    k_dw<<<BW_ * 2, 256, smD>>>(dw_w, dw_b, bn_g, bn_b, bn_m, bn_v);
    // G2: 1x1 conv: g_d @ pr_w^T + pr_b -> g_xcw
    k_gemm<256,false><<<dim3(1, MT), 256, smG>>>(pd, nullptr, pr_w, pr_w, 1<<30,
                                                 pr_b, pxcw, 128);
    // A: attention + LN -> g_xat2
    k_attn<<<BW_, 256, smA>>>(rpb, an_g, an_be);
    // G4: concat(g_xat2, g_xcw) @ po_w^T + po_b -> out
    k_gemm<256,true><<<dim3(2, MT), 256, smG>>>(pxat2, pxcw, po_w, po_w, 1<<30,
                                                po_b, (float*)d_out, 256);
}

// round 8
// speedup vs baseline: 1.4680x; 1.2379x over previous
#include <cuda_runtime.h>
#include <cuda_fp16.h>
#include <cstdint>

#define BW_   2048
#define NTOK  49
#define DIMC  256
#define C2    128
#define NH    8
#define M_TOT (BW_*NTOK)     // 100352
#define EPSV  1e-5f

// fp16 GEMM smem geometry (u32 words)
#define ASTRW 20              // A: 16 data words (32 halves) + 4 pad per row
#define WSTRW 136             // B: 128 n-cols + 8 pad per k-pair row
#define ASZW  (128*ASTRW)
#define WSZW  (16*WSTRW)

// ---------------- scratch (all half) ----------------
__device__ __half g_y1  [(size_t)M_TOT*384];
__device__ __half g_xat [(size_t)M_TOT*C2];
__device__ __half g_xc  [(size_t)M_TOT*DIMC];
__device__ __half g_d   [(size_t)M_TOT*DIMC];
__device__ __half g_qkv [(size_t)M_TOT*384];
__device__ __half g_xcw [(size_t)M_TOT*C2];
__device__ __half g_xat2[(size_t)M_TOT*C2];
// packed half weights: [pa;pc](384x256) | qkv(384x128) | pr(128x256) | po(256x256)
#define WOFF1 0
#define WOFF3 98304
#define WOFF2 147456
#define WOFF4 180224
__device__ __half g_wh[245760];

__device__ __forceinline__ float wsum(float v) {
    #pragma unroll
    for (int o = 16; o; o >>= 1) v += __shfl_xor_sync(0xffffffffu, v, o);
    return v;
}
__device__ __forceinline__ uint32_t h2u(float a, float b) {
    __half2 h = __floats2half2_rn(a, b);
    uint32_t u; *(__half2*)&u = h; return u;
}
__device__ __forceinline__ float2 h2f(__half2 h) { return __half22float2(h); }
__device__ __forceinline__ void mma16(float* c, const uint32_t* a,
                                      uint32_t b0, uint32_t b1) {
    asm volatile(
        "mma.sync.aligned.m16n8k16.row.col.f32.f16.f16.f32 "
        "{%0,%1,%2,%3},{%4,%5,%6,%7},{%8,%9},{%0,%1,%2,%3};"
        : "+f"(c[0]), "+f"(c[1]), "+f"(c[2]), "+f"(c[3])
        : "r"(a[0]), "r"(a[1]), "r"(a[2]), "r"(a[3]), "r"(b0), "r"(b1));
}

// ================= W0: fp32 -> fp16 weight pack =================
__global__ __launch_bounds__(256)
void k_wconv(const float* __restrict__ pa_w, const float* __restrict__ pc_w,
             const float* __restrict__ qkv_w, const float* __restrict__ pr_w,
             const float* __restrict__ po_w)
{
    const int seg = blockIdx.y;
    const int idx4 = blockIdx.x * 256 + threadIdx.x;
    const int sz4[4] = {24576, 12288, 8192, 16384};
    if (idx4 >= sz4[seg]) return;
    const int fi = idx4 * 4;
    const float* src; __half* dst;
    if (seg == 0) { src = (fi < 32768) ? pa_w + fi : pc_w + (fi - 32768); dst = g_wh + WOFF1 + fi; }
    else if (seg == 1) { src = qkv_w + fi; dst = g_wh + WOFF3 + fi; }
    else if (seg == 2) { src = pr_w  + fi; dst = g_wh + WOFF2 + fi; }
    else               { src = po_w  + fi; dst = g_wh + WOFF4 + fi; }
    float4 v = *(const float4*)src;
    __half2* d2 = (__half2*)dst;
    d2[0] = __floats2half2_rn(v.x, v.y);
    d2[1] = __floats2half2_rn(v.z, v.w);
}

// ============== fp16 tensor GEMM: C[M,N] = A[M,K] @ W^T (+bias) ==========
// 128x128 CTA tile; 8 warps each m32 x n64; k-chunks of 32 (2 x k16 steps).
template<int K, bool SPLITA, bool AHALF, bool OUTF32>
__global__ __launch_bounds__(256)
void k_gemm(const void* __restrict__ A0v, const void* __restrict__ A1v,
            const __half* __restrict__ W,
            const float* __restrict__ bias, void* __restrict__ Cv, int N)
{
    extern __shared__ uint32_t smu[];
    uint32_t* Asm = smu;               // [2][ASZW]
    uint32_t* Wsm = smu + 2 * ASZW;    // [2][WSZW]
    const int tid = threadIdx.x;
    const int m0 = blockIdx.y * 128, n0 = blockIdx.x * 128;
    constexpr int NCH = K / 32;
    const int lane = tid & 31, wid = tid >> 5;
    const int g = lane >> 2, r = lane & 3;
    const int mw = (wid & 3) * 32, nw = (wid >> 2) * 64;

    const int srow = tid >> 1, shalf = tid & 1;   // staging: row, 16-half piece
    const __half* wrowp = W + (size_t)(n0 + srow) * K + shalf * 16;

    uint4 ua[2], uw[2];
    auto loadAB = [&](int ch) {
        const int kk = ch * 32 + shalf * 16;
        if (AHALF) {
            const __half* ap;
            if (SPLITA) ap = (kk < 128) ? ((const __half*)A0v + (size_t)(m0 + srow) * 128 + kk)
                                        : ((const __half*)A1v + (size_t)(m0 + srow) * 128 + kk - 128);
            else        ap = (const __half*)A0v + (size_t)(m0 + srow) * K + kk;
            ua[0] = *(const uint4*)ap;
            ua[1] = *(const uint4*)(ap + 8);
        } else {
            const float* ap = (const float*)A0v + (size_t)(m0 + srow) * K + kk;
            float4 f0 = ((const float4*)ap)[0], f1 = ((const float4*)ap)[1];
            float4 f2 = ((const float4*)ap)[2], f3 = ((const float4*)ap)[3];
            ua[0] = make_uint4(h2u(f0.x, f0.y), h2u(f0.z, f0.w),
                               h2u(f1.x, f1.y), h2u(f1.z, f1.w));
            ua[1] = make_uint4(h2u(f2.x, f2.y), h2u(f2.z, f2.w),
                               h2u(f3.x, f3.y), h2u(f3.z, f3.w));
        }
        const __half* wp = wrowp + ch * 32;
        uw[0] = *(const uint4*)wp;
        uw[1] = *(const uint4*)(wp + 8);
    };
    auto storeAB = [&](int buf) {
        uint32_t* Ab = Asm + buf * ASZW;
        uint32_t* Wb = Wsm + buf * WSZW;
        *(uint4*)(Ab + srow * ASTRW + shalf * 8)     = ua[0];
        *(uint4*)(Ab + srow * ASTRW + shalf * 8 + 4) = ua[1];
        const uint32_t uws[8] = { uw[0].x, uw[0].y, uw[0].z, uw[0].w,
                                  uw[1].x, uw[1].y, uw[1].z, uw[1].w };
        #pragma unroll
        for (int j = 0; j < 8; ++j)
            Wb[(shalf * 8 + j) * WSTRW + srow] = uws[j];
    };

    float acc[2][8][4];
    #pragma unroll
    for (int mt = 0; mt < 2; ++mt)
        #pragma unroll
        for (int nt = 0; nt < 8; ++nt)
            #pragma unroll
            for (int e = 0; e < 4; ++e) acc[mt][nt][e] = 0.f;

    loadAB(0);
    storeAB(0);
    __syncthreads();

    for (int ch = 0; ch < NCH; ++ch) {
        if (ch + 1 < NCH) loadAB(ch + 1);
        const uint32_t* Ab = Asm + (ch & 1) * ASZW;
        const uint32_t* Wb = Wsm + (ch & 1) * WSZW;
        #pragma unroll
        for (int ks = 0; ks < 2; ++ks) {
            const int kp = ks * 8;
            uint32_t af[2][4];
            #pragma unroll
            for (int mt = 0; mt < 2; ++mt) {
                const int rb = mw + mt * 16;
                af[mt][0] = Ab[(rb + g)     * ASTRW + kp + r];
                af[mt][1] = Ab[(rb + g + 8) * ASTRW + kp + r];
                af[mt][2] = Ab[(rb + g)     * ASTRW + kp + r + 4];
                af[mt][3] = Ab[(rb + g + 8) * ASTRW + kp + r + 4];
            }
            #pragma unroll
            for (int nt = 0; nt < 8; ++nt) {
                const int cb = nw + nt * 8 + g;
                const uint32_t b0 = Wb[(kp + r)     * WSTRW + cb];
                const uint32_t b1 = Wb[(kp + r + 4) * WSTRW + cb];
                mma16(acc[0][nt], af[0], b0, b1);
                mma16(acc[1][nt], af[1], b0, b1);
            }
        }
        if (ch + 1 < NCH) {
            __syncthreads();
            storeAB((ch + 1) & 1);
            __syncthreads();
        }
    }

    #pragma unroll
    for (int mt = 0; mt < 2; ++mt) {
        #pragma unroll
        for (int nt = 0; nt < 8; ++nt) {
            const int col = n0 + nw + nt * 8 + 2 * r;
            float b0 = 0.f, b1 = 0.f;
            if (bias) { b0 = bias[col]; b1 = bias[col + 1]; }
            const int r0 = m0 + mw + mt * 16 + g;
            if (OUTF32) {
                float* C = (float*)Cv;
                *(float2*)(C + (size_t)r0 * N + col)       =
                    make_float2(acc[mt][nt][0] + b0, acc[mt][nt][1] + b1);
                *(float2*)(C + (size_t)(r0 + 8) * N + col) =
                    make_float2(acc[mt][nt][2] + b0, acc[mt][nt][3] + b1);
            } else {
                __half* C = (__half*)Cv;
                *(__half2*)(C + (size_t)r0 * N + col)       =
                    __floats2half2_rn(acc[mt][nt][0] + b0, acc[mt][nt][1] + b1);
                *(__half2*)(C + (size_t)(r0 + 8) * N + col) =
                    __floats2half2_rn(acc[mt][nt][2] + b0, acc[mt][nt][3] + b1);
            }
        }
    }
}

// ================= E1: dual LayerNorm epilogue of G1 =================
__global__ __launch_bounds__(256)
void k_ln1(const float* __restrict__ pa_b, const float* __restrict__ pa_g,
           const float* __restrict__ pa_be,
           const float* __restrict__ pc_b, const float* __restrict__ pc_g,
           const float* __restrict__ pc_be)
{
    const int row  = blockIdx.x * 8 + (threadIdx.x >> 5);
    const int lane = threadIdx.x & 31;
    const __half2* y2 = (const __half2*)(g_y1 + (size_t)row * 384);

    // attention branch: halves 0..127
    float2 f0 = h2f(y2[lane * 2]), f1 = h2f(y2[lane * 2 + 1]);
    float va[4] = { f0.x, f0.y, f1.x, f1.y };
    float4 b = ((const float4*)pa_b)[lane];
    va[0] += b.x; va[1] += b.y; va[2] += b.z; va[3] += b.w;
    float m = wsum(va[0] + va[1] + va[2] + va[3]) * (1.f / 128.f);
    float q = 0.f;
    #pragma unroll
    for (int k = 0; k < 4; ++k) { va[k] -= m; q += va[k] * va[k]; }
    float inv = rsqrtf(wsum(q) * (1.f / 128.f) + EPSV);
    float4 gg = ((const float4*)pa_g)[lane];
    float4 be = ((const float4*)pa_be)[lane];
    __half2* xa2 = (__half2*)(g_xat + (size_t)row * 128);
    xa2[lane * 2]     = __floats2half2_rn(va[0] * inv * gg.x + be.x, va[1] * inv * gg.y + be.y);
    xa2[lane * 2 + 1] = __floats2half2_rn(va[2] * inv * gg.z + be.z, va[3] * inv * gg.w + be.w);

    // cnn branch: halves 128..383
    float c[8];
    #pragma unroll
    for (int k = 0; k < 4; ++k) {
        float2 t = h2f(y2[64 + lane * 4 + k]);
        c[2 * k] = t.x; c[2 * k + 1] = t.y;
    }
    float4 b0 = ((const float4*)pc_b)[lane * 2], b1 = ((const float4*)pc_b)[lane * 2 + 1];
    c[0] += b0.x; c[1] += b0.y; c[2] += b0.z; c[3] += b0.w;
    c[4] += b1.x; c[5] += b1.y; c[6] += b1.z; c[7] += b1.w;
    float s = 0.f;
    #pragma unroll
    for (int k = 0; k < 8; ++k) s += c[k];
    m = wsum(s) * (1.f / 256.f);
    q = 0.f;
    #pragma unroll
    for (int k = 0; k < 8; ++k) { c[k] -= m; q += c[k] * c[k]; }
    inv = rsqrtf(wsum(q) * (1.f / 256.f) + EPSV);
    float4 g0 = ((const float4*)pc_g)[lane * 2],  g1 = ((const float4*)pc_g)[lane * 2 + 1];
    float4 e0 = ((const float4*)pc_be)[lane * 2], e1 = ((const float4*)pc_be)[lane * 2 + 1];
    __half2* xc2 = (__half2*)(g_xc + (size_t)row * 256);
    xc2[lane * 4]     = __floats2half2_rn(c[0] * inv * g0.x + e0.x, c[1] * inv * g0.y + e0.y);
    xc2[lane * 4 + 1] = __floats2half2_rn(c[2] * inv * g0.z + e0.z, c[3] * inv * g0.w + e0.w);
    xc2[lane * 4 + 2] = __floats2half2_rn(c[4] * inv * g1.x + e1.x, c[5] * inv * g1.y + e1.y);
    xc2[lane * 4 + 3] = __floats2half2_rn(c[6] * inv * g1.z + e1.z, c[7] * inv * g1.w + e1.w);
}

// ================= D: depthwise 3x3 + BN + GELU =================
__global__ __launch_bounds__(256)
void k_dw(const float* __restrict__ dw_w, const float* __restrict__ dw_b,
          const float* __restrict__ bn_g, const float* __restrict__ bn_b,
          const float* __restrict__ bn_m, const float* __restrict__ bn_v)
{
    extern __shared__ float sm[];   // 81 pixels x 128 ch (fp32)
    const int bw = blockIdx.x >> 1, half = blockIdx.x & 1;
    const int cb = half * 128;
    const int tid = threadIdx.x;
    const int b = bw >> 6, wi = bw & 63, wr = wi >> 3, wc = wi & 7;

    for (int i = tid; i < 81 * 16; i += 256) {
        int pix = i >> 4, c8 = i & 15;
        int gy = wr * 7 + pix / 9 - 1, gx = wc * 7 + pix % 9 - 1;
        float4 o0 = make_float4(0.f, 0.f, 0.f, 0.f), o1 = o0;
        if ((unsigned)gy < 56u && (unsigned)gx < 56u) {
            int wn = b * 64 + (gy / 7) * 8 + gx / 7;
            int tk = (gy % 7) * 7 + gx % 7;
            uint4 u = *(const uint4*)(g_xc + ((size_t)wn * 49 + tk) * 256 + cb + c8 * 8);
            float2 p0 = h2f(*(__half2*)&u.x), p1 = h2f(*(__half2*)&u.y);
            float2 p2 = h2f(*(__half2*)&u.z), p3 = h2f(*(__half2*)&u.w);
            o0 = make_float4(p0.x, p0.y, p1.x, p1.y);
            o1 = make_float4(p2.x, p2.y, p3.x, p3.y);
        }
        *(float4*)(sm + pix * 128 + c8 * 8)     = o0;
        *(float4*)(sm + pix * 128 + c8 * 8 + 4) = o1;
    }
    __syncthreads();

    const int c  = tid & 127;
    const int ph = tid >> 7;
    const int cg = cb + c;
    float w[9];
    #pragma unroll
    for (int j = 0; j < 9; ++j) w[j] = dw_w[cg * 9 + j];
    const float sc = bn_g[cg] * rsqrtf(bn_v[cg] + EPSV);
    const float sh = bn_b[cg] - bn_m[cg] * sc;
    const float db = dw_b[cg];
    const float* smc = sm + c;
    __half* outc = g_d + (size_t)bw * 49 * 256 + cb + c;

    auto dopix = [&](int p) {
        const int oy = p / 7, ox = p % 7;   // compile-time constants
        float acc = db;
        #pragma unroll
        for (int dy = 0; dy < 3; ++dy)
            #pragma unroll
            for (int dx = 0; dx < 3; ++dx)
                acc += w[dy * 3 + dx] * smc[((oy + dy) * 9 + ox + dx) * 128];
        float v = acc * sc + sh;
        outc[p * 256] = __float2half_rn(0.5f * v * (1.0f + erff(v * 0.70710678118654752f)));
    };
    if (ph == 0) {
        #pragma unroll
        for (int q = 0; q < 25; ++q) dopix(2 * q);
    } else {
        #pragma unroll
        for (int q = 0; q < 24; ++q) dopix(2 * q + 1);
    }
}

// ================= A: windowed MHSA + LN =================
__global__ __launch_bounds__(256)
void k_attn(const float* __restrict__ rpb,
            const float* __restrict__ an_g, const float* __restrict__ an_be)
{
    extern __shared__ float sm[];
    float* kvs  = sm;                 // 49*256 (k | v) fp32
    float* ss   = sm + 49 * 256;      // 8*32*53 scores
    float* rpbs = ss + 8 * 32 * 53;   // 1352
    const int bw = blockIdx.x, tid = threadIdx.x;
    const int h = tid >> 5, lane = tid & 31;
    const __half* qkvw = g_qkv + (size_t)bw * 49 * 384;

    for (int i = tid; i < 49 * 32; i += 256) {
        int rr = i >> 5, cc = i & 31;
        uint4 u = *(const uint4*)(qkvw + rr * 384 + 128 + cc * 8);
        float2 p0 = h2f(*(__half2*)&u.x), p1 = h2f(*(__half2*)&u.y);
        float2 p2 = h2f(*(__half2*)&u.z), p3 = h2f(*(__half2*)&u.w);
        *(float4*)(kvs + rr * 256 + cc * 8)     = make_float4(p0.x, p0.y, p1.x, p1.y);
        *(float4*)(kvs + rr * 256 + cc * 8 + 4) = make_float4(p2.x, p2.y, p3.x, p3.y);
    }
    for (int i = tid; i < 1352; i += 256) rpbs[i] = rpb[i];
    __syncthreads();

    float o[2][16];
    #pragma unroll
    for (int pass = 0; pass < 2; ++pass) {
        const int n = pass * 32 + lane;
        if (n < 49) {
            const __half2* qp = (const __half2*)(qkvw + n * 384 + h * 16);
            float q[16];
            #pragma unroll
            for (int k = 0; k < 8; ++k) {
                float2 t = h2f(qp[k]);
                q[2 * k] = t.x; q[2 * k + 1] = t.y;
            }
            const int yn = n / 7, xn = n % 7;
            float* sr = ss + (h * 32 + lane) * 53;
            float mx = -1e30f;
            #pragma unroll 7
            for (int m2 = 0; m2 < 49; ++m2) {
                const float4* kr = (const float4*)(kvs + m2 * 256 + h * 16);
                float4 k0 = kr[0], k1 = kr[1], k2 = kr[2], k3 = kr[3];
                float s = q[0]*k0.x + q[1]*k0.y + q[2]*k0.z + q[3]*k0.w
                        + q[4]*k1.x + q[5]*k1.y + q[6]*k1.z + q[7]*k1.w
                        + q[8]*k2.x + q[9]*k2.y + q[10]*k2.z + q[11]*k2.w
                        + q[12]*k3.x + q[13]*k3.y + q[14]*k3.z + q[15]*k3.w;
                int dy = yn - m2 / 7 + 6, dx = xn - m2 % 7 + 6;
                s = s * 0.25f + rpbs[(dy * 13 + dx) * NH + h];
                sr[m2] = s; mx = fmaxf(mx, s);
            }
            float sum = 0.f;
            #pragma unroll 7
            for (int m2 = 0; m2 < 49; ++m2) {
                float e = __expf(sr[m2] - mx);
                sr[m2] = e; sum += e;
            }
            const float inv = 1.f / sum;
            float* op = o[pass];
            #pragma unroll
            for (int d = 0; d < 16; ++d) op[d] = 0.f;
            #pragma unroll 7
            for (int m2 = 0; m2 < 49; ++m2) {
                const float p = sr[m2];
                const float4* vr = (const float4*)(kvs + m2 * 256 + 128 + h * 16);
                float4 v0 = vr[0], v1 = vr[1], v2 = vr[2], v3 = vr[3];
                op[0]  += p * v0.x; op[1]  += p * v0.y; op[2]  += p * v0.z; op[3]  += p * v0.w;
                op[4]  += p * v1.x; op[5]  += p * v1.y; op[6]  += p * v1.z; op[7]  += p * v1.w;
                op[8]  += p * v2.x; op[9]  += p * v2.y; op[10] += p * v2.z; op[11] += p * v2.w;
                op[12] += p * v3.x; op[13] += p * v3.y; op[14] += p * v3.z; op[15] += p * v3.w;
            }
            #pragma unroll
            for (int d = 0; d < 16; ++d) op[d] *= inv;
        }
    }
    __syncthreads();
    float* xo = kvs;
    #pragma unroll
    for (int pass = 0; pass < 2; ++pass) {
        const int n = pass * 32 + lane;
        if (n < 49) {
            #pragma unroll
            for (int d = 0; d < 16; ++d) xo[n * 128 + h * 16 + d] = o[pass][d];
        }
    }
    __syncthreads();

    for (int rr = h; rr < 49; rr += 8) {
        float4 v = *(float4*)(xo + rr * 128 + lane * 4);
        float m = wsum(v.x + v.y + v.z + v.w) * (1.f / 128.f);
        v.x -= m; v.y -= m; v.z -= m; v.w -= m;
        float inv = rsqrtf(wsum(v.x*v.x + v.y*v.y + v.z*v.z + v.w*v.w) * (1.f / 128.f) + EPSV);
        float4 gg = ((const float4*)an_g)[lane];
        float4 be = ((const float4*)an_be)[lane];
        __half2* oa = (__half2*)(g_xat2 + ((size_t)bw * 49 + rr) * 128);
        oa[lane * 2]     = __floats2half2_rn(v.x * inv * gg.x + be.x, v.y * inv * gg.y + be.y);
        oa[lane * 2 + 1] = __floats2half2_rn(v.z * inv * gg.z + be.z, v.w * inv * gg.w + be.w);
    }
}

// ================= host launch =================
extern "C" void kernel_launch(void* const* d_in, const int* in_sizes, int n_in,
                              void* d_out, int out_size)
{
    const float* x     = (const float*)d_in[0];
    const float* rpb   = (const float*)d_in[1];
    const float* pa_w  = (const float*)d_in[2];
    const float* pa_b  = (const float*)d_in[3];
    const float* pa_g  = (const float*)d_in[4];
    const float* pa_be = (const float*)d_in[5];
    const float* pc_w  = (const float*)d_in[6];
    const float* pc_b  = (const float*)d_in[7];
    const float* pc_g  = (const float*)d_in[8];
    const float* pc_be = (const float*)d_in[9];
    const float* dw_w  = (const float*)d_in[10];
    const float* dw_b  = (const float*)d_in[11];
    const float* bn_g  = (const float*)d_in[12];
    const float* bn_b  = (const float*)d_in[13];
    const float* bn_m  = (const float*)d_in[14];
    const float* bn_v  = (const float*)d_in[15];
    const float* pr_w  = (const float*)d_in[16];
    const float* pr_b  = (const float*)d_in[17];
    const float* qkv_w = (const float*)d_in[18];
    const float* qkv_b = (const float*)d_in[19];
    const float* an_g  = (const float*)d_in[20];
    const float* an_be = (const float*)d_in[21];
    const float* po_w  = (const float*)d_in[22];
    const float* po_b  = (const float*)d_in[23];

    __half *py1, *pxat, *pxc, *pd, *pqkv, *pxcw, *pxat2, *pwh;
    cudaGetSymbolAddress((void**)&py1,   g_y1);
    cudaGetSymbolAddress((void**)&pxat,  g_xat);
    cudaGetSymbolAddress((void**)&pxc,   g_xc);
    cudaGetSymbolAddress((void**)&pd,    g_d);
    cudaGetSymbolAddress((void**)&pqkv,  g_qkv);
    cudaGetSymbolAddress((void**)&pxcw,  g_xcw);
    cudaGetSymbolAddress((void**)&pxat2, g_xat2);
    cudaGetSymbolAddress((void**)&pwh,   g_wh);

    const int smG = (2 * ASZW + 2 * WSZW) * 4;    // 37,888
    const int smD = 81 * 128 * 4;                 // 41,472
    const int smA = (49*256 + 8*32*53 + 1352) * 4;// 109,856

    cudaFuncSetAttribute((const void*)k_gemm<256,false,false,false>, cudaFuncAttributeMaxDynamicSharedMemorySize, smG);
    cudaFuncSetAttribute((const void*)k_gemm<128,false,true,false>,  cudaFuncAttributeMaxDynamicSharedMemorySize, smG);
    cudaFuncSetAttribute((const void*)k_gemm<256,false,true,false>,  cudaFuncAttributeMaxDynamicSharedMemorySize, smG);
    cudaFuncSetAttribute((const void*)k_gemm<256,true,true,true>,    cudaFuncAttributeMaxDynamicSharedMemorySize, smG);
    cudaFuncSetAttribute((const void*)k_dw,   cudaFuncAttributeMaxDynamicSharedMemorySize, smD);
    cudaFuncSetAttribute((const void*)k_attn, cudaFuncAttributeMaxDynamicSharedMemorySize, smA);

    const int MT = M_TOT / 128;   // 784

    // W0: pack weights to half
    k_wconv<<<dim3(96, 4), 256>>>(pa_w, pc_w, qkv_w, pr_w, po_w);
    // G1: x @ [pa_w; pc_w]^T -> g_y1 (half; bias deferred to LN)
    k_gemm<256,false,false,false><<<dim3(3, MT), 256, smG>>>(x, nullptr, pwh + WOFF1,
                                                             nullptr, py1, 384);
    // E1: dual LN -> g_xat, g_xc (half)
    k_ln1<<<M_TOT/8, 256>>>(pa_b, pa_g, pa_be, pc_b, pc_g, pc_be);
    // G3: qkv = g_xat @ qkv_w^T + qkv_b
    k_gemm<128,false,true,false><<<dim3(3, MT), 256, smG>>>(pxat, nullptr, pwh + WOFF3,
                                                            qkv_b, pqkv, 384);
    // D: dwconv + BN + GELU -> g_d
    k_dw<<<BW_ * 2, 256, smD>>>(dw_w, dw_b, bn_g, bn_b, bn_m, bn_v);
    // G2: 1x1 conv: g_d @ pr_w^T + pr_b -> g_xcw
    k_gemm<256,false,true,false><<<dim3(1, MT), 256, smG>>>(pd, nullptr, pwh + WOFF2,
                                                            pr_b, pxcw, 128);
    // A: attention + LN -> g_xat2
    k_attn<<<BW_, 256, smA>>>(rpb, an_g, an_be);
    // G4: concat(g_xat2, g_xcw) @ po_w^T + po_b -> out (float)
    k_gemm<256,true,true,true><<<dim3(2, MT), 256, smG>>>(pxat2, pxcw, pwh + WOFF4,
                                                          po_b, d_out, 256);
}